// round 14
// baseline (speedup 1.0000x reference)
#include <cuda_runtime.h>
#include <cuda_bf16.h>
#include <cstdint>

// d_in[0] = values     f32 [1048576, 8]
// d_in[1] = weights    f32 [65536, 8, 8]
// d_in[2] = input_idx  i32 [E]
// d_in[3] = weight_idx i32 [E]
// out     = f32 [E, 8]
//
// R11 configuration (best: 75.5us), restored after R12's prefetch regression
// (prefetched idx lines were evicted before wrap-around reuse -> double DRAM
// traffic; +4 MIO instr/batch).
//   - 8 lanes/edge, 2 edge chains (e, e+half_E)
//   - warp-batched coalesced idx loads (__ldcs), packed weight idx
//     (wA | wB<<16) -> 3 distribution shfls per inner iteration
//   - lane k takes W float4 #k and #(k+8): unique full-128B-line-coverage
//     mapping (2 wf/edge for W); x half (k&1): 1 wf/edge
//   - single-shfl pair reduction (send what the xor-1 partner needs)
//   - gathers: L2::evict_last cache hint; stores: __stcs streaming
//   - 1184 CTAs (148 SMs x 8), __launch_bounds__(256,8) pins 32 regs
// R13 adds: loop-invariant gather base pointers hoisted (vbase, wbase_k,
// wbase_k8) so each gather address is one IMAD.WIDE — ALU-pipe shave only.

__device__ __forceinline__ float4 ldg_el(const float4* p, uint64_t pol) {
    float4 v;
    asm("ld.global.nc.L2::cache_hint.v4.f32 {%0,%1,%2,%3}, [%4], %5;"
        : "=f"(v.x), "=f"(v.y), "=f"(v.z), "=f"(v.w)
        : "l"(p), "l"(pol));
    return v;
}

__device__ __forceinline__ float dot4(float4 a, float4 b) {
    float r = a.x * b.x;
    r = fmaf(a.y, b.y, r);
    r = fmaf(a.z, b.z, r);
    r = fmaf(a.w, b.w, r);
    return r;
}

__global__ __launch_bounds__(256, 8) void edge_mm_kernel(
    const float4* __restrict__ values,    // [NUM_VALUES*2]  float4
    const float4* __restrict__ weights,   // [NUM_WEIGHTS*16] float4
    const int*    __restrict__ input_idx,
    const int*    __restrict__ weight_idx,
    float*        __restrict__ out,
    int half_E,
    int nfull)                            // half_E rounded down to 32
{
    int tid = blockIdx.x * blockDim.x + threadIdx.x;
    int lane = threadIdx.x & 31;
    int warpG = tid >> 5;
    int totalWarps = (gridDim.x * blockDim.x) >> 5;
    int k = lane & 7;                     // lane role within edge
    int grp = lane >> 3;                  // edge slot within inner iteration
    int half = k & 1;
    int pos = (k >> 1) + (half << 2);

    uint64_t pol;
    asm("createpolicy.fractional.L2::evict_last.b64 %0, 1.0;" : "=l"(pol));

    // Loop-invariant gather bases: one IMAD.WIDE per gather inside the loop
    const float4* vbase    = values + half;     // + vi*2
    const float4* wbase_k  = weights + k;       // + wi*16
    const float4* wbase_k8 = weights + k + 8;   // + wi*16

    for (int base = warpG * 32; base < nfull; base += totalWarps * 32) {
        // Coalesced idx batch: 32 edges per chain, 4 x 128B loads.
        int inA = __ldcs(input_idx + base + lane);
        int wA  = __ldcs(weight_idx + base + lane);
        int inB = __ldcs(input_idx + base + half_E + lane);
        int wB  = __ldcs(weight_idx + base + half_E + lane);
        // weight_idx < 65536: both chains' weight idx in one register
        unsigned wAB = (unsigned)wA | ((unsigned)wB << 16);

#pragma unroll 1
        for (int j = 0; j < 8; j++) {
            int src = j * 4 + grp;
            int vi0 = __shfl_sync(0xFFFFFFFFu, inA, src);
            int vi1 = __shfl_sync(0xFFFFFFFFu, inB, src);
            unsigned wp = __shfl_sync(0xFFFFFFFFu, wAB, src);
            int wi0 = (int)(wp & 0xFFFFu);
            int wi1 = (int)(wp >> 16);

            float4 xa  = ldg_el(vbase + vi0 * 2, pol);
            float4 xb  = ldg_el(vbase + vi1 * 2, pol);
            float4 wa0 = ldg_el(wbase_k  + wi0 * 16, pol);
            float4 wa1 = ldg_el(wbase_k8 + wi0 * 16, pol);
            float4 wb0 = ldg_el(wbase_k  + wi1 * 16, pol);
            float4 wb1 = ldg_el(wbase_k8 + wi1 * 16, pol);

            float pa0 = dot4(wa0, xa);
            float pa1 = dot4(wa1, xa);
            float pb0 = dot4(wb0, xb);
            float pb1 = dot4(wb1, xb);

            // Single-shfl pair reduction: send what the xor-1 partner needs.
            float sendA = half ? pa0 : pa1;
            float sendB = half ? pb0 : pb1;
            float recvA = __shfl_xor_sync(0xFFFFFFFFu, sendA, 1);
            float recvB = __shfl_xor_sync(0xFFFFFFFFu, sendB, 1);
            float ya = (half ? pa1 : pa0) + recvA;
            float yb = (half ? pb1 : pb0) + recvB;

            int e0 = base + src;
            __stcs(out + e0 * 8 + pos, ya);
            __stcs(out + (e0 + half_E) * 8 + pos, yb);
        }
    }

    // Tail (half_E % 32 != 0; never taken for E = 4194304)
    int e = nfull + (tid >> 3);
    if (e < half_E) {
        int vi0 = __ldg(input_idx + e);
        int wi0 = __ldg(weight_idx + e);
        int vi1 = __ldg(input_idx + e + half_E);
        int wi1 = __ldg(weight_idx + e + half_E);
        float4 xa  = ldg_el(vbase + vi0 * 2, pol);
        float4 xb  = ldg_el(vbase + vi1 * 2, pol);
        float4 wa0 = ldg_el(wbase_k  + wi0 * 16, pol);
        float4 wa1 = ldg_el(wbase_k8 + wi0 * 16, pol);
        float4 wb0 = ldg_el(wbase_k  + wi1 * 16, pol);
        float4 wb1 = ldg_el(wbase_k8 + wi1 * 16, pol);
        float pa0 = dot4(wa0, xa);
        float pa1 = dot4(wa1, xa);
        float pb0 = dot4(wb0, xb);
        float pb1 = dot4(wb1, xb);
        float sendA = half ? pa0 : pa1;
        float sendB = half ? pb0 : pb1;
        float recvA = __shfl_xor_sync(0xFFFFFFFFu, sendA, 1);
        float recvB = __shfl_xor_sync(0xFFFFFFFFu, sendB, 1);
        __stcs(out + e * 8 + pos, (half ? pa1 : pa0) + recvA);
        __stcs(out + (e + half_E) * 8 + pos, (half ? pb1 : pb0) + recvB);
    }
}

extern "C" void kernel_launch(void* const* d_in, const int* in_sizes, int n_in,
                              void* d_out, int out_size)
{
    const float4* values  = (const float4*)d_in[0];
    const float4* weights = (const float4*)d_in[1];
    const int* input_idx  = (const int*)d_in[2];
    const int* weight_idx = (const int*)d_in[3];
    float* out = (float*)d_out;

    int E = in_sizes[2];
    int half_E = E >> 1;                  // E even (4194304)
    int nfull = half_E & ~31;

    int threads = 256;
    int blocks = 1184;                    // 148 SMs * 8 resident CTAs
    long long needed = ((long long)half_E * 8 + threads - 1) / threads;
    if (needed < blocks) blocks = (int)needed;

    edge_mm_kernel<<<blocks, threads>>>(values, weights, input_idx, weight_idx,
                                        out, half_E, nfull);
}

// round 15
// speedup vs baseline: 1.0531x; 1.0531x over previous
#include <cuda_runtime.h>
#include <cuda_bf16.h>
#include <cstdint>

// d_in[0] = values     f32 [1048576, 8]
// d_in[1] = weights    f32 [65536, 8, 8]
// d_in[2] = input_idx  i32 [E]
// d_in[3] = weight_idx i32 [E]
// out     = f32 [E, 8]
//
// R11 configuration — measured session best (75.5us), restored byte-for-byte
// after R13 (address hoisting) perturbed the SASS schedule and regressed 6%.
//   - 8 lanes/edge, 2 edge chains (e, e+half_E)
//   - warp-batched coalesced idx loads (__ldcs), packed weight idx
//     (wA | wB<<16) -> 3 distribution shfls per inner iteration
//   - lane k takes W float4 #k and #(k+8): the unique full-128B-line-coverage
//     mapping (2 wf/edge for W); x half (k&1): 1 wf/edge
//   - single-shfl pair reduction (send what the xor-1 partner needs)
//   - gathers: L2::evict_last cache hint; stores: __stcs streaming
//   - 1184 CTAs (148 SMs x 8 resident, single wave), __launch_bounds__(256,8)
//     pinning 32 regs / 97% occupancy
// Per-8-edge MIO budget: W 16 wf + x 8 + st 2 + shfl 5 + idx 0.5 = 31.5 wf
// (~62us chip floor); measured 75.5us = floor + L2-hit latency exposure.

__device__ __forceinline__ float4 ldg_el(const float4* p, uint64_t pol) {
    float4 v;
    asm("ld.global.nc.L2::cache_hint.v4.f32 {%0,%1,%2,%3}, [%4], %5;"
        : "=f"(v.x), "=f"(v.y), "=f"(v.z), "=f"(v.w)
        : "l"(p), "l"(pol));
    return v;
}

__device__ __forceinline__ float dot4(float4 a, float4 b) {
    float r = a.x * b.x;
    r = fmaf(a.y, b.y, r);
    r = fmaf(a.z, b.z, r);
    r = fmaf(a.w, b.w, r);
    return r;
}

__global__ __launch_bounds__(256, 8) void edge_mm_kernel(
    const float4* __restrict__ values,    // [NUM_VALUES*2]  float4
    const float4* __restrict__ weights,   // [NUM_WEIGHTS*16] float4
    const int*    __restrict__ input_idx,
    const int*    __restrict__ weight_idx,
    float*        __restrict__ out,
    int half_E,
    int nfull)                            // half_E rounded down to 32
{
    int tid = blockIdx.x * blockDim.x + threadIdx.x;
    int lane = threadIdx.x & 31;
    int warpG = tid >> 5;
    int totalWarps = (gridDim.x * blockDim.x) >> 5;
    int k = lane & 7;                     // lane role within edge
    int grp = lane >> 3;                  // edge slot within inner iteration
    int half = k & 1;
    int pos = (k >> 1) + (half << 2);

    uint64_t pol;
    asm("createpolicy.fractional.L2::evict_last.b64 %0, 1.0;" : "=l"(pol));

    for (int base = warpG * 32; base < nfull; base += totalWarps * 32) {
        // Coalesced idx batch: 32 edges per chain, 4 x 128B loads.
        int inA = __ldcs(input_idx + base + lane);
        int wA  = __ldcs(weight_idx + base + lane);
        int inB = __ldcs(input_idx + base + half_E + lane);
        int wB  = __ldcs(weight_idx + base + half_E + lane);
        // weight_idx < 65536: both chains' weight idx in one register
        unsigned wAB = (unsigned)wA | ((unsigned)wB << 16);

#pragma unroll 1
        for (int j = 0; j < 8; j++) {
            int src = j * 4 + grp;
            int vi0 = __shfl_sync(0xFFFFFFFFu, inA, src);
            int vi1 = __shfl_sync(0xFFFFFFFFu, inB, src);
            unsigned wp = __shfl_sync(0xFFFFFFFFu, wAB, src);
            int wi0 = (int)(wp & 0xFFFFu);
            int wi1 = (int)(wp >> 16);

            float4 xa = ldg_el(values + vi0 * 2 + half, pol);
            float4 xb = ldg_el(values + vi1 * 2 + half, pol);
            const float4* W0 = weights + wi0 * 16;
            const float4* W1 = weights + wi1 * 16;
            float4 wa0 = ldg_el(W0 + k, pol);
            float4 wa1 = ldg_el(W0 + k + 8, pol);
            float4 wb0 = ldg_el(W1 + k, pol);
            float4 wb1 = ldg_el(W1 + k + 8, pol);

            float pa0 = dot4(wa0, xa);
            float pa1 = dot4(wa1, xa);
            float pb0 = dot4(wb0, xb);
            float pb1 = dot4(wb1, xb);

            // Single-shfl pair reduction: send what the xor-1 partner needs.
            float sendA = half ? pa0 : pa1;
            float sendB = half ? pb0 : pb1;
            float recvA = __shfl_xor_sync(0xFFFFFFFFu, sendA, 1);
            float recvB = __shfl_xor_sync(0xFFFFFFFFu, sendB, 1);
            float ya = (half ? pa1 : pa0) + recvA;
            float yb = (half ? pb1 : pb0) + recvB;

            int e0 = base + src;
            __stcs(out + e0 * 8 + pos, ya);
            __stcs(out + (e0 + half_E) * 8 + pos, yb);
        }
    }

    // Tail (half_E % 32 != 0; never taken for E = 4194304)
    int e = nfull + (tid >> 3);
    if (e < half_E) {
        int vi0 = __ldg(input_idx + e);
        int wi0 = __ldg(weight_idx + e);
        int vi1 = __ldg(input_idx + e + half_E);
        int wi1 = __ldg(weight_idx + e + half_E);
        float4 xa = ldg_el(values + vi0 * 2 + half, pol);
        float4 xb = ldg_el(values + vi1 * 2 + half, pol);
        float4 wa0 = ldg_el(weights + wi0 * 16 + k, pol);
        float4 wa1 = ldg_el(weights + wi0 * 16 + k + 8, pol);
        float4 wb0 = ldg_el(weights + wi1 * 16 + k, pol);
        float4 wb1 = ldg_el(weights + wi1 * 16 + k + 8, pol);
        float pa0 = dot4(wa0, xa);
        float pa1 = dot4(wa1, xa);
        float pb0 = dot4(wb0, xb);
        float pb1 = dot4(wb1, xb);
        float sendA = half ? pa0 : pa1;
        float sendB = half ? pb0 : pb1;
        float recvA = __shfl_xor_sync(0xFFFFFFFFu, sendA, 1);
        float recvB = __shfl_xor_sync(0xFFFFFFFFu, sendB, 1);
        __stcs(out + e * 8 + pos, (half ? pa1 : pa0) + recvA);
        __stcs(out + (e + half_E) * 8 + pos, (half ? pb1 : pb0) + recvB);
    }
}

extern "C" void kernel_launch(void* const* d_in, const int* in_sizes, int n_in,
                              void* d_out, int out_size)
{
    const float4* values  = (const float4*)d_in[0];
    const float4* weights = (const float4*)d_in[1];
    const int* input_idx  = (const int*)d_in[2];
    const int* weight_idx = (const int*)d_in[3];
    float* out = (float*)d_out;

    int E = in_sizes[2];
    int half_E = E >> 1;                  // E even (4194304)
    int nfull = half_E & ~31;

    int threads = 256;
    int blocks = 1184;                    // 148 SMs * 8 resident CTAs
    long long needed = ((long long)half_E * 8 + threads - 1) / threads;
    if (needed < blocks) blocks = (int)needed;

    edge_mm_kernel<<<blocks, threads>>>(values, weights, input_idx, weight_idx,
                                        out, half_E, nfull);
}